// round 8
// baseline (speedup 1.0000x reference)
#include <cuda_runtime.h>
#include <cuda_bf16.h>

// Problem constants (B=8, T=4096, C=512)
#define B_DIM 8
#define T_DIM 4096
#define C_DIM 512
#define CPB   32                 // channels per block
#define CG_PB 8                  // float4 channel-groups per block
#define NSEG  128                // time segments per block
#define SEG   32                 // timesteps per segment (NSEG*SEG = T)
#define XS    (C_DIM / 4)        // float4 stride per timestep in x
#define OS    (C_DIM * 2 / 4)    // float4 stride per timestep in out

// 4 independent complex recurrence steps (one per channel in the float4)
__device__ __forceinline__ void step4(float4& hr, float4& hi,
                                      const float4 Ar, const float4 Ai,
                                      const float4 xv) {
    float4 nr, ni;
    nr.x = fmaf(hr.x, Ar.x, fmaf(-hi.x, Ai.x, xv.x));
    ni.x = fmaf(hr.x, Ai.x, hi.x * Ar.x);
    nr.y = fmaf(hr.y, Ar.y, fmaf(-hi.y, Ai.y, xv.y));
    ni.y = fmaf(hr.y, Ai.y, hi.y * Ar.y);
    nr.z = fmaf(hr.z, Ar.z, fmaf(-hi.z, Ai.z, xv.z));
    ni.z = fmaf(hr.z, Ai.z, hi.z * Ar.z);
    nr.w = fmaf(hr.w, Ar.w, fmaf(-hi.w, Ai.w, xv.w));
    ni.w = fmaf(hr.w, Ai.w, hi.w * Ar.w);
    hr = nr; hi = ni;
}

__global__ __launch_bounds__(1024, 1)
void stateful_recurrent_kernel(const float* __restrict__ x,
                               const float* __restrict__ Ar_g,
                               const float* __restrict__ Ai_g,
                               const float* __restrict__ h0r_g,
                               const float* __restrict__ h0i_g,
                               float* __restrict__ out) {
    // finals, then (in-place) segment-start states
    __shared__ float s_r[NSEG][CPB];
    __shared__ float s_i[NSEG][CPB];

    const int cg   = threadIdx.x & (CG_PB - 1);   // 0..7
    const int seg  = threadIdx.x >> 3;            // 0..127
    const int b    = blockIdx.x >> 4;
    const int slab = blockIdx.x & 15;
    const int c0   = slab * CPB + cg * 4;         // first of this thread's 4 channels

    const float4 Ar = *reinterpret_cast<const float4*>(Ar_g + c0);
    const float4 Ai = *reinterpret_cast<const float4*>(Ai_g + c0);

    const float4* xp = reinterpret_cast<const float4*>(x + (size_t)b * T_DIM * C_DIM)
                       + (c0 >> 2);
    const int t0 = seg * SEG;

    // ---------------- Phase A: zero-start local scan of this segment --------------
    float4 hr = make_float4(0.f, 0.f, 0.f, 0.f);
    float4 hi = make_float4(0.f, 0.f, 0.f, 0.f);
    {
        const float4* xq = xp + (size_t)t0 * XS;
        #pragma unroll
        for (int j = 0; j < SEG; j += 4) {
            float4 x0 = xq[(size_t)(j + 0) * XS];
            float4 x1 = xq[(size_t)(j + 1) * XS];
            float4 x2 = xq[(size_t)(j + 2) * XS];
            float4 x3 = xq[(size_t)(j + 3) * XS];
            step4(hr, hi, Ar, Ai, x0);
            step4(hr, hi, Ar, Ai, x1);
            step4(hr, hi, Ar, Ai, x2);
            step4(hr, hi, Ar, Ai, x3);
        }
    }
    s_r[seg][cg * 4 + 0] = hr.x;  s_i[seg][cg * 4 + 0] = hi.x;
    s_r[seg][cg * 4 + 1] = hr.y;  s_i[seg][cg * 4 + 1] = hi.y;
    s_r[seg][cg * 4 + 2] = hr.z;  s_i[seg][cg * 4 + 2] = hi.z;
    s_r[seg][cg * 4 + 3] = hr.w;  s_i[seg][cg * 4 + 3] = hi.w;
    __syncthreads();

    // -------- Phase B: serial prefix over the 128 segments (32 threads, 1 ch each) --------
    if (threadIdx.x < CPB) {
        const int ch = threadIdx.x;
        const int c  = slab * CPB + ch;
        float ar = Ar_g[c], ai = Ai_g[c];
        // A^SEG = A^32 via 5 complex squarings
        float pr = ar, pi = ai;
        #pragma unroll
        for (int s = 0; s < 5; s++) {
            float nr = pr * pr - pi * pi;
            float ni = 2.f * pr * pi;
            pr = nr; pi = ni;
        }
        float cr = h0r_g[(size_t)b * C_DIM + c];
        float ci = h0i_g[(size_t)b * C_DIM + c];
        // software-pipelined: prefetch next final while the cfma chain runs
        float fr = s_r[0][ch], fi = s_i[0][ch];
        #pragma unroll 4
        for (int s = 0; s < NSEG; s++) {
            float frn = 0.f, fin = 0.f;
            if (s + 1 < NSEG) { frn = s_r[s + 1][ch]; fin = s_i[s + 1][ch]; }
            s_r[s][ch] = cr;  s_i[s][ch] = ci;   // overwrite final with start (in place)
            float nr = fmaf(pr, cr, fmaf(-pi, ci, fr));
            float ni = fmaf(pr, ci, fmaf(pi, cr, fi));
            cr = nr; ci = ni;
            fr = frn; fi = fin;
        }
    }
    __syncthreads();

    // ---------------- Phase C: replay from correct start, write out ----------------
    hr.x = s_r[seg][cg * 4 + 0];  hi.x = s_i[seg][cg * 4 + 0];
    hr.y = s_r[seg][cg * 4 + 1];  hi.y = s_i[seg][cg * 4 + 1];
    hr.z = s_r[seg][cg * 4 + 2];  hi.z = s_i[seg][cg * 4 + 2];
    hr.w = s_r[seg][cg * 4 + 3];  hi.w = s_i[seg][cg * 4 + 3];

    {
        const float4* xq = xp + (size_t)t0 * XS;
        float4* op = reinterpret_cast<float4*>(out + ((size_t)b * T_DIM * C_DIM + c0) * 2)
                     + (size_t)t0 * OS;
        #pragma unroll
        for (int j = 0; j < SEG; j += 4) {
            float4 xv[4];
            xv[0] = xq[(size_t)(j + 0) * XS];
            xv[1] = xq[(size_t)(j + 1) * XS];
            xv[2] = xq[(size_t)(j + 2) * XS];
            xv[3] = xq[(size_t)(j + 3) * XS];
            #pragma unroll
            for (int k = 0; k < 4; k++) {
                step4(hr, hi, Ar, Ai, xv[k]);
                float4 o0 = make_float4(hr.x, hi.x, hr.y, hi.y);
                float4 o1 = make_float4(hr.z, hi.z, hr.w, hi.w);
                size_t r = (size_t)(j + k) * OS;
                op[r + 0] = o0;
                op[r + 1] = o1;
            }
        }
    }
}

extern "C" void kernel_launch(void* const* d_in, const int* in_sizes, int n_in,
                              void* d_out, int out_size) {
    const float* x   = (const float*)d_in[0];   // (B, T, C)
    const float* Ar  = (const float*)d_in[1];   // (C,)
    const float* Ai  = (const float*)d_in[2];   // (C,)
    const float* h0r = (const float*)d_in[3];   // (B, C)
    const float* h0i = (const float*)d_in[4];   // (B, C)
    float* out = (float*)d_out;                 // (B, T, C, 2)

    dim3 grid(B_DIM * (C_DIM / CPB));           // 8 * 16 = 128 blocks
    dim3 block(1024);
    stateful_recurrent_kernel<<<grid, block>>>(x, Ar, Ai, h0r, h0i, out);
}

// round 11
// speedup vs baseline: 1.8974x; 1.8974x over previous
#include <cuda_runtime.h>
#include <cuda_bf16.h>

// Problem constants (B=8, T=4096, C=512)
#define B_DIM 8
#define T_DIM 4096
#define C_DIM 512
#define CPB   32                 // channels per block
#define PAIRS 16                 // channel-pairs per block (2 ch per thread)
#define NSEG  64                 // time segments per block
#define SEG   64                 // timesteps per segment (NSEG*SEG = T)
#define UNR   8                  // load batch depth
#define XS2   (C_DIM / 2)        // float2 stride per timestep in x
#define OS4   (C_DIM * 2 / 4)    // float4 stride per timestep in out

// 2 independent complex recurrence steps (ch0 = .x, ch1 = .y)
__device__ __forceinline__ void step2(float2& hr, float2& hi,
                                      const float2 Ar, const float2 Ai,
                                      const float2 xv) {
    float2 nr, ni;
    nr.x = fmaf(hr.x, Ar.x, fmaf(-hi.x, Ai.x, xv.x));
    ni.x = fmaf(hr.x, Ai.x, hi.x * Ar.x);
    nr.y = fmaf(hr.y, Ar.y, fmaf(-hi.y, Ai.y, xv.y));
    ni.y = fmaf(hr.y, Ai.y, hi.y * Ar.y);
    hr = nr; hi = ni;
}

__global__ __launch_bounds__(1024, 1)
void stateful_recurrent_kernel(const float* __restrict__ x,
                               const float* __restrict__ Ar_g,
                               const float* __restrict__ Ai_g,
                               const float* __restrict__ h0r_g,
                               const float* __restrict__ h0i_g,
                               float* __restrict__ out) {
    // Phase A finals, then (in place) segment-start states
    __shared__ float s_r[NSEG][CPB];
    __shared__ float s_i[NSEG][CPB];

    const int pair = threadIdx.x & (PAIRS - 1);   // 0..15
    const int seg  = threadIdx.x >> 4;            // 0..63
    const int b    = blockIdx.x >> 4;
    const int slab = blockIdx.x & 15;
    const int c0   = slab * CPB + pair * 2;       // first of this thread's 2 channels

    const float2 Ar = *reinterpret_cast<const float2*>(Ar_g + c0);
    const float2 Ai = *reinterpret_cast<const float2*>(Ai_g + c0);

    const float2* xp = reinterpret_cast<const float2*>(x + (size_t)b * T_DIM * C_DIM)
                       + (c0 >> 1);
    const int t0 = seg * SEG;

    // ---------------- Phase A: zero-start local scan of this segment --------------
    float2 hr = make_float2(0.f, 0.f);
    float2 hi = make_float2(0.f, 0.f);
    {
        const float2* xq = xp + (size_t)t0 * XS2;
        #pragma unroll 1
        for (int j = 0; j < SEG; j += UNR) {
            float2 xv[UNR];
            #pragma unroll
            for (int k = 0; k < UNR; k++)
                xv[k] = xq[(size_t)(j + k) * XS2];
            #pragma unroll
            for (int k = 0; k < UNR; k++)
                step2(hr, hi, Ar, Ai, xv[k]);
        }
    }
    s_r[seg][pair * 2 + 0] = hr.x;  s_i[seg][pair * 2 + 0] = hi.x;
    s_r[seg][pair * 2 + 1] = hr.y;  s_i[seg][pair * 2 + 1] = hi.y;
    __syncthreads();

    // -------- Phase B: serial prefix over 64 segments (32 threads, 1 channel each) --------
    if (threadIdx.x < CPB) {
        const int ch = threadIdx.x;
        const int c  = slab * CPB + ch;
        float ar = Ar_g[c], ai = Ai_g[c];
        // A^SEG = A^64 via 6 complex squarings
        float pr = ar, pi = ai;
        #pragma unroll
        for (int s = 0; s < 6; s++) {
            float nr = pr * pr - pi * pi;
            float ni = 2.f * pr * pi;
            pr = nr; pi = ni;
        }
        float cr = h0r_g[(size_t)b * C_DIM + c];
        float ci = h0i_g[(size_t)b * C_DIM + c];
        float fr = s_r[0][ch], fi = s_i[0][ch];
        #pragma unroll 4
        for (int s = 0; s < NSEG; s++) {
            float frn = 0.f, fin = 0.f;
            if (s + 1 < NSEG) { frn = s_r[s + 1][ch]; fin = s_i[s + 1][ch]; }
            s_r[s][ch] = cr;  s_i[s][ch] = ci;   // overwrite final with start, in place
            float nr = fmaf(pr, cr, fmaf(-pi, ci, fr));
            float ni = fmaf(pr, ci, fmaf(pi, cr, fi));
            cr = nr; ci = ni;
            fr = frn; fi = fin;
        }
    }
    __syncthreads();

    // ---------------- Phase C: replay from correct start, write out ----------------
    hr.x = s_r[seg][pair * 2 + 0];  hi.x = s_i[seg][pair * 2 + 0];
    hr.y = s_r[seg][pair * 2 + 1];  hi.y = s_i[seg][pair * 2 + 1];
    {
        const float2* xq = xp + (size_t)t0 * XS2;
        float4* op = reinterpret_cast<float4*>(out + ((size_t)b * T_DIM * C_DIM) * 2)
                     + (size_t)t0 * OS4 + (c0 >> 1);
        #pragma unroll 1
        for (int j = 0; j < SEG; j += UNR) {
            float2 xv[UNR];
            #pragma unroll
            for (int k = 0; k < UNR; k++)
                xv[k] = xq[(size_t)(j + k) * XS2];
            #pragma unroll
            for (int k = 0; k < UNR; k++) {
                step2(hr, hi, Ar, Ai, xv[k]);
                op[(size_t)(j + k) * OS4] = make_float4(hr.x, hi.x, hr.y, hi.y);
            }
        }
    }
}

extern "C" void kernel_launch(void* const* d_in, const int* in_sizes, int n_in,
                              void* d_out, int out_size) {
    const float* x   = (const float*)d_in[0];   // (B, T, C)
    const float* Ar  = (const float*)d_in[1];   // (C,)
    const float* Ai  = (const float*)d_in[2];   // (C,)
    const float* h0r = (const float*)d_in[3];   // (B, C)
    const float* h0i = (const float*)d_in[4];   // (B, C)
    float* out = (float*)d_out;                 // (B, T, C, 2)

    dim3 grid(B_DIM * (C_DIM / CPB));           // 8 * 16 = 128 blocks
    dim3 block(1024);
    stateful_recurrent_kernel<<<grid, block>>>(x, Ar, Ai, h0r, h0i, out);
}